// round 1
// baseline (speedup 1.0000x reference)
#include <cuda_runtime.h>

#define BB 4
#define TT 2048
#define CC 1024
#define HH 16
#define DD 64
#define M_TOT (BB*TT)   // 8192

// Scratch (device globals: allocation-free rule)
__device__ float g_Q[BB*HH*TT*DD];    // [B,H,T,D]
__device__ float g_K[BB*HH*TT*DD];
__device__ float g_V[BB*HH*TT*DD];
__device__ float g_Att[BB*TT*CC];     // attention out in [B,T,C]

// ---------------------------------------------------------------------------
// GEMM: Out[M,N] = A[M,1024] @ W[1024,N] + bias[N]
// mode 0: plain row-major write to Out
// mode 1: N=3072 QKV scatter into g_Q/g_K/g_V ([B,H,T,D])
// Tiles: 128x128x16, 256 threads, 8x8 per thread (split-N columns).
// ---------------------------------------------------------------------------
__global__ __launch_bounds__(256, 2)
void gemm_kernel(const float* __restrict__ A, const float* __restrict__ W,
                 const float* __restrict__ bias, float* __restrict__ Out,
                 float* __restrict__ Qp, float* __restrict__ Kp, float* __restrict__ Vp,
                 int N, int mode)
{
    __shared__ float As[16][128];   // [k][m] transposed
    __shared__ float Bs[16][128];   // [k][n]

    const int tid = threadIdx.x;
    const int tx  = tid & 15;       // 0..15
    const int ty  = tid >> 4;       // 0..15
    const int n0  = blockIdx.x * 128;
    const int m0  = blockIdx.y * 128;

    float acc[8][8];
#pragma unroll
    for (int i = 0; i < 8; ++i)
#pragma unroll
        for (int j = 0; j < 8; ++j) acc[i][j] = 0.f;

    for (int k0 = 0; k0 < 1024; k0 += 16) {
        // load A tile (128 rows x 16 k) and B tile (16 k x 128 n)
#pragma unroll
        for (int p = 0; p < 2; ++p) {
            int idx = tid + p * 256;            // 0..511
            int r   = idx >> 2;                 // 0..127
            int kq  = (idx & 3) * 4;            // 0,4,8,12
            float4 a = *(const float4*)&A[(m0 + r) * 1024 + k0 + kq];
            As[kq + 0][r] = a.x;
            As[kq + 1][r] = a.y;
            As[kq + 2][r] = a.z;
            As[kq + 3][r] = a.w;
            int kr = idx >> 5;                  // 0..15
            int nc = (idx & 31) * 4;            // 0..124
            *(float4*)&Bs[kr][nc] = *(const float4*)&W[(k0 + kr) * N + n0 + nc];
        }
        __syncthreads();

#pragma unroll
        for (int kk = 0; kk < 16; ++kk) {
            float4 a0 = *(const float4*)&As[kk][ty * 8];
            float4 a1 = *(const float4*)&As[kk][ty * 8 + 4];
            float4 b0 = *(const float4*)&Bs[kk][tx * 4];
            float4 b1 = *(const float4*)&Bs[kk][tx * 4 + 64];
            float ar[8] = {a0.x, a0.y, a0.z, a0.w, a1.x, a1.y, a1.z, a1.w};
            float br[8] = {b0.x, b0.y, b0.z, b0.w, b1.x, b1.y, b1.z, b1.w};
#pragma unroll
            for (int i = 0; i < 8; ++i)
#pragma unroll
                for (int j = 0; j < 8; ++j)
                    acc[i][j] += ar[i] * br[j];
        }
        __syncthreads();
    }

    // epilogue
#pragma unroll
    for (int i = 0; i < 8; ++i) {
        int m = m0 + ty * 8 + i;
#pragma unroll
        for (int half = 0; half < 2; ++half) {
            int n = n0 + half * 64 + tx * 4;
            float4 bv = *(const float4*)&bias[n];
            float4 v;
            v.x = acc[i][half * 4 + 0] + bv.x;
            v.y = acc[i][half * 4 + 1] + bv.y;
            v.z = acc[i][half * 4 + 2] + bv.z;
            v.w = acc[i][half * 4 + 3] + bv.w;
            if (mode == 0) {
                *(float4*)&Out[m * N + n] = v;
            } else {
                int sec = n >> 10;              // 0:Q 1:K 2:V
                int rem = n & 1023;
                int h   = rem >> 6;
                int d   = rem & 63;
                int b   = m >> 11;
                int t   = m & 2047;
                float* dst = (sec == 0) ? Qp : (sec == 1) ? Kp : Vp;
                *(float4*)&dst[(((b * HH + h) * TT + t) << 6) + d] = v;
            }
        }
    }
}

// ---------------------------------------------------------------------------
// Flash attention (causal, fp32, online softmax).
// Block: one (b,h,q-tile of 64). 256 threads as 16x16; 4x4 micro-tiles.
// Smem: Qs[64][64], Ks[64][68] (reused as S/P), Vs[64][64], rowA[64].
// ---------------------------------------------------------------------------
#define ATTN_SMEM_FLOATS (64*64 + 64*68 + 64*64 + 64)
#define ATTN_SMEM_BYTES  (ATTN_SMEM_FLOATS * 4)

__global__ __launch_bounds__(256, 2)
void attn_kernel(const float* __restrict__ Q, const float* __restrict__ K,
                 const float* __restrict__ V, float* __restrict__ O)
{
    extern __shared__ float sm[];
    float* Qs   = sm;                     // [64][64]
    float* Ks   = sm + 4096;              // [64][68]  (also S/P buffer)
    float* Vs   = sm + 4096 + 4352;       // [64][64]
    float* rowA = Vs + 4096;              // [64]

    const float NEG_INF = -__int_as_float(0x7f800000);

    const int tid  = threadIdx.x;
    const int tx   = tid & 15;
    const int ty   = tid >> 4;
    const int qt   = blockIdx.x;          // q tile 0..31
    const int head = blockIdx.y;
    const int b    = blockIdx.z;
    const int q0   = qt * 64;

    const int base = (b * HH + head) * TT * DD;
    const float* Qb = Q + base;
    const float* Kb = K + base;
    const float* Vb = V + base;

    // load Q tile [64][64]
#pragma unroll
    for (int p = 0; p < 4; ++p) {
        int idx = tid + p * 256;           // 0..1023
        int r   = idx >> 4;                // 0..63
        int d0  = (idx & 15) * 4;          // 0..60
        *(float4*)&Qs[r * 64 + d0] = *(const float4*)&Qb[(q0 + r) * DD + d0];
    }

    float o[4][4];
#pragma unroll
    for (int i = 0; i < 4; ++i)
#pragma unroll
        for (int j = 0; j < 4; ++j) o[i][j] = 0.f;

    float m_prev = NEG_INF, l_prev = 0.f;
    const int r_own = tid >> 2;            // 0..63
    const int c_own = (tid & 3) * 16;      // 0,16,32,48

    for (int jt = 0; jt <= qt; ++jt) {
        const int k0 = jt * 64;
        __syncthreads();   // prior-iter P/V reads done (also orders Qs stores on iter 0)

        // load K,V tiles
#pragma unroll
        for (int p = 0; p < 4; ++p) {
            int idx = tid + p * 256;
            int r   = idx >> 4;
            int d0  = (idx & 15) * 4;
            *(float4*)&Ks[r * 68 + d0] = *(const float4*)&Kb[(k0 + r) * DD + d0];
            *(float4*)&Vs[r * 64 + d0] = *(const float4*)&Vb[(k0 + r) * DD + d0];
        }
        __syncthreads();

        // S = Q . K^T  (4x4 per thread, inner over d)
        float s[4][4];
#pragma unroll
        for (int i = 0; i < 4; ++i)
#pragma unroll
            for (int j = 0; j < 4; ++j) s[i][j] = 0.f;

#pragma unroll
        for (int d0 = 0; d0 < 64; d0 += 4) {
            float4 qa[4], kb4[4];
#pragma unroll
            for (int i = 0; i < 4; ++i) qa[i]  = *(const float4*)&Qs[(ty * 4 + i) * 64 + d0];
#pragma unroll
            for (int j = 0; j < 4; ++j) kb4[j] = *(const float4*)&Ks[(tx * 4 + j) * 68 + d0];
#pragma unroll
            for (int i = 0; i < 4; ++i)
#pragma unroll
                for (int j = 0; j < 4; ++j)
                    s[i][j] += qa[i].x * kb4[j].x + qa[i].y * kb4[j].y
                             + qa[i].z * kb4[j].z + qa[i].w * kb4[j].w;
        }
        __syncthreads();   // all Ks reads done -> safe to overwrite with S

        // write scaled+masked S into the Ks buffer as S[r][c]
#pragma unroll
        for (int i = 0; i < 4; ++i) {
            int qi = q0 + ty * 4 + i;
#pragma unroll
            for (int j = 0; j < 4; ++j) {
                int kj = k0 + tx * 4 + j;
                Ks[(ty * 4 + i) * 68 + tx * 4 + j] = (kj <= qi) ? s[i][j] * 0.125f : NEG_INF;
            }
        }
        __syncthreads();

        // online softmax: 4 threads per row, 16 cols each
        float vals[16];
        float mloc = NEG_INF;
#pragma unroll
        for (int c2 = 0; c2 < 16; ++c2) {
            vals[c2] = Ks[r_own * 68 + c_own + c2];
            mloc = fmaxf(mloc, vals[c2]);
        }
        mloc = fmaxf(mloc, __shfl_xor_sync(0xffffffffu, mloc, 1));
        mloc = fmaxf(mloc, __shfl_xor_sync(0xffffffffu, mloc, 2));
        float m_new = fmaxf(m_prev, mloc);
        float alpha = __expf(m_prev - m_new);   // m_prev=-inf -> 0
        float ssum = 0.f;
#pragma unroll
        for (int c2 = 0; c2 < 16; ++c2) {
            float pv = __expf(vals[c2] - m_new);
            Ks[r_own * 68 + c_own + c2] = pv;
            ssum += pv;
        }
        ssum += __shfl_xor_sync(0xffffffffu, ssum, 1);
        ssum += __shfl_xor_sync(0xffffffffu, ssum, 2);
        l_prev = l_prev * alpha + ssum;
        m_prev = m_new;
        if ((tid & 3) == 0) rowA[r_own] = alpha;
        __syncthreads();

        // O = O*alpha + P @ V
        float al[4];
#pragma unroll
        for (int i = 0; i < 4; ++i) al[i] = rowA[ty * 4 + i];
#pragma unroll
        for (int i = 0; i < 4; ++i)
#pragma unroll
            for (int j = 0; j < 4; ++j) o[i][j] *= al[i];

#pragma unroll
        for (int kk0 = 0; kk0 < 64; kk0 += 4) {
            float4 pa[4], vb4[4];
#pragma unroll
            for (int i = 0; i < 4; ++i) pa[i]  = *(const float4*)&Ks[(ty * 4 + i) * 68 + kk0];
#pragma unroll
            for (int u = 0; u < 4; ++u) vb4[u] = *(const float4*)&Vs[(kk0 + u) * 64 + tx * 4];
#pragma unroll
            for (int i = 0; i < 4; ++i) {
                o[i][0] += pa[i].x * vb4[0].x + pa[i].y * vb4[1].x + pa[i].z * vb4[2].x + pa[i].w * vb4[3].x;
                o[i][1] += pa[i].x * vb4[0].y + pa[i].y * vb4[1].y + pa[i].z * vb4[2].y + pa[i].w * vb4[3].y;
                o[i][2] += pa[i].x * vb4[0].z + pa[i].y * vb4[1].z + pa[i].z * vb4[2].z + pa[i].w * vb4[3].z;
                o[i][3] += pa[i].x * vb4[0].w + pa[i].y * vb4[1].w + pa[i].z * vb4[2].w + pa[i].w * vb4[3].w;
            }
        }
    }

    // normalize and write out in [B,T,C] layout
    __syncthreads();
    if ((tid & 3) == 0) rowA[r_own] = 1.f / l_prev;
    __syncthreads();
#pragma unroll
    for (int i = 0; i < 4; ++i) {
        float inv = rowA[ty * 4 + i];
        int q = q0 + ty * 4 + i;
        float4 v;
        v.x = o[i][0] * inv;
        v.y = o[i][1] * inv;
        v.z = o[i][2] * inv;
        v.w = o[i][3] * inv;
        *(float4*)&O[(b * TT + q) * CC + head * DD + tx * 4] = v;
    }
}

// ---------------------------------------------------------------------------
extern "C" void kernel_launch(void* const* d_in, const int* in_sizes, int n_in,
                              void* d_out, int out_size)
{
    const float* x    = (const float*)d_in[0];  // [4,2048,1024]
    const float* Wqkv = (const float*)d_in[1];  // [1024,3072]
    const float* bqkv = (const float*)d_in[2];  // [3072]
    const float* Wo   = (const float*)d_in[3];  // [1024,1024]
    const float* bo   = (const float*)d_in[4];  // [1024]
    float* out = (float*)d_out;                 // [4,2048,1024]

    float *gQ, *gK, *gV, *gAtt;
    cudaGetSymbolAddress((void**)&gQ,   g_Q);
    cudaGetSymbolAddress((void**)&gK,   g_K);
    cudaGetSymbolAddress((void**)&gV,   g_V);
    cudaGetSymbolAddress((void**)&gAtt, g_Att);

    // 1) QKV projection + scatter to [B,H,T,D]
    gemm_kernel<<<dim3(3072 / 128, M_TOT / 128), 256>>>(
        x, Wqkv, bqkv, nullptr, gQ, gK, gV, 3072, 1);

    // 2) causal flash attention -> [B,T,C]
    cudaFuncSetAttribute(attn_kernel, cudaFuncAttributeMaxDynamicSharedMemorySize,
                         ATTN_SMEM_BYTES);
    attn_kernel<<<dim3(TT / 64, HH, BB), 256, ATTN_SMEM_BYTES>>>(gQ, gK, gV, gAtt);

    // 3) output projection
    gemm_kernel<<<dim3(1024 / 128, M_TOT / 128), 256>>>(
        gAtt, Wo, bo, out, nullptr, nullptr, nullptr, 1024, 0);
}

// round 2
// speedup vs baseline: 2.4929x; 2.4929x over previous
#include <cuda_runtime.h>
#include <cstdint>

#define BB 4
#define TT 2048
#define CC 1024
#define HH 16
#define DD 64
#define M_TOT (BB*TT)   // 8192

// Scratch (device globals: allocation-free rule)
__device__ float g_Q[BB*HH*TT*DD];    // [B,H,T,D]
__device__ float g_K[BB*HH*TT*DD];
__device__ float g_V[BB*HH*TT*DD];
__device__ float g_Att[BB*TT*CC];     // attention out in [B,T,C]

__device__ __forceinline__ uint32_t f2tf32(float x) {
    uint32_t y;
    asm("cvt.rna.tf32.f32 %0, %1;" : "=r"(y) : "f"(x));
    return y;
}

__device__ __forceinline__ void mma_tf32(float& c0, float& c1, float& c2, float& c3,
                                         uint32_t a0, uint32_t a1, uint32_t a2, uint32_t a3,
                                         uint32_t b0, uint32_t b1)
{
    asm volatile(
        "mma.sync.aligned.m16n8k8.row.col.f32.tf32.tf32.f32 "
        "{%0,%1,%2,%3}, {%4,%5,%6,%7}, {%8,%9}, {%0,%1,%2,%3};"
        : "+f"(c0), "+f"(c1), "+f"(c2), "+f"(c3)
        : "r"(a0), "r"(a1), "r"(a2), "r"(a3), "r"(b0), "r"(b1));
}

// ---------------------------------------------------------------------------
// tf32 GEMM: Out[M,N] = A[M,1024] @ W[1024,N] + bias[N]
// Tile 128x128x32, 256 threads (8 warps, 4x2), warp tile 32x64.
// mode 0: row-major write; mode 1: QKV scatter to [B,H,T,D]
// ---------------------------------------------------------------------------
__global__ __launch_bounds__(256, 2)
void gemm_tf32(const float* __restrict__ A, const float* __restrict__ W,
               const float* __restrict__ bias, float* __restrict__ Out,
               float* __restrict__ Qp, float* __restrict__ Kp, float* __restrict__ Vp,
               int N, int mode)
{
    __shared__ uint32_t As[32][136];   // [k][m], pad to kill bank conflicts
    __shared__ uint32_t Bs[32][136];   // [k][n]

    const int tid  = threadIdx.x;
    const int wid  = tid >> 5;
    const int lane = tid & 31;
    const int g    = lane >> 2;        // 0..7
    const int tig  = lane & 3;         // 0..3
    const int wm   = wid & 3;          // 0..3 -> m offset wm*32
    const int wn   = wid >> 2;         // 0..1 -> n offset wn*64
    const int n0   = blockIdx.x * 128;
    const int m0   = blockIdx.y * 128;

    float acc[2][8][4];
#pragma unroll
    for (int mt = 0; mt < 2; ++mt)
#pragma unroll
        for (int nt = 0; nt < 8; ++nt)
#pragma unroll
            for (int q = 0; q < 4; ++q) acc[mt][nt][q] = 0.f;

    for (int k0 = 0; k0 < 1024; k0 += 32) {
        // fill smem: A tile 128m x 32k (transposed), B tile 32k x 128n
#pragma unroll
        for (int p = 0; p < 4; ++p) {
            int s = tid + p * 256;               // 0..1023
            int m  = s & 127;
            int kq = (s >> 7) * 4;               // 0,4,...,28
            float4 a = *(const float4*)&A[(m0 + m) * 1024 + k0 + kq];
            As[kq + 0][m] = f2tf32(a.x);
            As[kq + 1][m] = f2tf32(a.y);
            As[kq + 2][m] = f2tf32(a.z);
            As[kq + 3][m] = f2tf32(a.w);
            int n4 = (s & 31) * 4;
            int kr = s >> 5;                     // 0..31
            float4 b = *(const float4*)&W[(k0 + kr) * N + n0 + n4];
            uint4 bb;
            bb.x = f2tf32(b.x); bb.y = f2tf32(b.y);
            bb.z = f2tf32(b.z); bb.w = f2tf32(b.w);
            *(uint4*)&Bs[kr][n4] = bb;
        }
        __syncthreads();

#pragma unroll
        for (int ks = 0; ks < 4; ++ks) {
            const int kk = ks * 8;
            uint32_t af[2][4];
#pragma unroll
            for (int mt = 0; mt < 2; ++mt) {
                int mr = wm * 32 + mt * 16 + g;
                af[mt][0] = As[kk + tig    ][mr];
                af[mt][1] = As[kk + tig    ][mr + 8];
                af[mt][2] = As[kk + tig + 4][mr];
                af[mt][3] = As[kk + tig + 4][mr + 8];
            }
#pragma unroll
            for (int nt = 0; nt < 8; ++nt) {
                int nc = wn * 64 + nt * 8 + g;
                uint32_t b0 = Bs[kk + tig    ][nc];
                uint32_t b1 = Bs[kk + tig + 4][nc];
#pragma unroll
                for (int mt = 0; mt < 2; ++mt)
                    mma_tf32(acc[mt][nt][0], acc[mt][nt][1], acc[mt][nt][2], acc[mt][nt][3],
                             af[mt][0], af[mt][1], af[mt][2], af[mt][3], b0, b1);
            }
        }
        __syncthreads();
    }

    // epilogue: c0,c1 at (row g, col 2tig,2tig+1); c2,c3 at (row g+8)
#pragma unroll
    for (int mt = 0; mt < 2; ++mt) {
#pragma unroll
        for (int nt = 0; nt < 8; ++nt) {
            int col = n0 + wn * 64 + nt * 8 + tig * 2;
            float2 bv = *(const float2*)&bias[col];
            int r0 = m0 + wm * 32 + mt * 16 + g;
#pragma unroll
            for (int h = 0; h < 2; ++h) {
                int row = r0 + h * 8;
                float2 v;
                v.x = acc[mt][nt][h * 2 + 0] + bv.x;
                v.y = acc[mt][nt][h * 2 + 1] + bv.y;
                if (mode == 0) {
                    *(float2*)&Out[row * N + col] = v;
                } else {
                    int sec = col >> 10;           // 0:Q 1:K 2:V
                    int rem = col & 1023;
                    int hh  = rem >> 6;
                    int d   = rem & 63;
                    int b   = row >> 11;
                    int t   = row & 2047;
                    float* dst = (sec == 0) ? Qp : (sec == 1) ? Kp : Vp;
                    *(float2*)&dst[(((b * HH + hh) * TT + t) << 6) + d] = v;
                }
            }
        }
    }
}

// ---------------------------------------------------------------------------
// Flash attention (causal, tf32 mma, fp32 online softmax).
// Block: one (b, h, 64-row q tile). 256 threads = 8 warps (4m x 2n).
// Each warp: 16q x 32 cols of S / O.
// ---------------------------------------------------------------------------
#define AST 76   // smem row stride (floats): 76 -> conflict-free frag loads
#define ATTN_SMEM_FLOATS (4*64*AST + 64)
#define ATTN_SMEM_BYTES  (ATTN_SMEM_FLOATS * 4)

__global__ __launch_bounds__(256, 2)
void attn_tf32(const float* __restrict__ Q, const float* __restrict__ K,
               const float* __restrict__ V, float* __restrict__ O)
{
    extern __shared__ float sm[];
    uint32_t* Qs = (uint32_t*)sm;                  // [64][AST] tf32
    uint32_t* Ks = (uint32_t*)(sm + 64 * AST);     // [64][AST] tf32
    uint32_t* Vt = (uint32_t*)(sm + 2 * 64 * AST); // [d][kk] transposed, tf32
    float*    Ss = sm + 3 * 64 * AST;              // [64][AST] fp32 S -> tf32 P bits
    float*  rowA = sm + 4 * 64 * AST;              // [64]

    const float NEG_INF = -__int_as_float(0x7f800000);

    const int tid  = threadIdx.x;
    const int wid  = tid >> 5;
    const int lane = tid & 31;
    const int g    = lane >> 2;
    const int tig  = lane & 3;
    const int wm   = wid & 3;           // q offset wm*16
    const int wn   = wid >> 2;          // col offset wn*32
    const int qt   = blockIdx.x;
    const int head = blockIdx.y;
    const int b    = blockIdx.z;
    const int q0   = qt * 64;

    const int base = (b * HH + head) * TT * DD;
    const float* Qb = Q + base;
    const float* Kb = K + base;
    const float* Vb = V + base;

    // load Q tile -> tf32
#pragma unroll
    for (int p = 0; p < 4; ++p) {
        int idx = tid + p * 256;
        int r   = idx >> 4;
        int d0  = (idx & 15) * 4;
        float4 q = *(const float4*)&Qb[(q0 + r) * DD + d0];
        uint4 u;
        u.x = f2tf32(q.x); u.y = f2tf32(q.y);
        u.z = f2tf32(q.z); u.w = f2tf32(q.w);
        *(uint4*)&Qs[r * AST + d0] = u;
    }

    float o[4][4];
#pragma unroll
    for (int nt = 0; nt < 4; ++nt)
#pragma unroll
        for (int q = 0; q < 4; ++q) o[nt][q] = 0.f;

    float m_prev = NEG_INF, l_prev = 0.f;
    const int r_own = tid >> 2;          // 0..63
    const int c_own = (tid & 3) * 16;

    for (int jt = 0; jt <= qt; ++jt) {
        const int k0 = jt * 64;
        __syncthreads();   // prior-iter Ss/Vt reads done; Qs stores on iter 0

        // load K,V tiles (V transposed)
#pragma unroll
        for (int p = 0; p < 4; ++p) {
            int idx = tid + p * 256;
            int r   = idx >> 4;
            int d0  = (idx & 15) * 4;
            float4 kv = *(const float4*)&Kb[(k0 + r) * DD + d0];
            uint4 u;
            u.x = f2tf32(kv.x); u.y = f2tf32(kv.y);
            u.z = f2tf32(kv.z); u.w = f2tf32(kv.w);
            *(uint4*)&Ks[r * AST + d0] = u;
            float4 vv = *(const float4*)&Vb[(k0 + r) * DD + d0];
            Vt[(d0 + 0) * AST + r] = f2tf32(vv.x);
            Vt[(d0 + 1) * AST + r] = f2tf32(vv.y);
            Vt[(d0 + 2) * AST + r] = f2tf32(vv.z);
            Vt[(d0 + 3) * AST + r] = f2tf32(vv.w);
        }
        __syncthreads();

        // S = Q . K^T  (per warp: 16q x 32k, 4 n8-tiles)
        float sc[4][4];
#pragma unroll
        for (int nt = 0; nt < 4; ++nt)
#pragma unroll
            for (int q = 0; q < 4; ++q) sc[nt][q] = 0.f;

#pragma unroll
        for (int d0 = 0; d0 < 64; d0 += 8) {
            int qr = (wm * 16 + g) * AST;
            uint32_t a0 = Qs[qr + d0 + tig];
            uint32_t a1 = Qs[qr + 8 * AST + d0 + tig];
            uint32_t a2 = Qs[qr + d0 + tig + 4];
            uint32_t a3 = Qs[qr + 8 * AST + d0 + tig + 4];
#pragma unroll
            for (int nt = 0; nt < 4; ++nt) {
                int j = (wn * 32 + nt * 8 + g) * AST;
                uint32_t b0 = Ks[j + d0 + tig];
                uint32_t b1 = Ks[j + d0 + tig + 4];
                mma_tf32(sc[nt][0], sc[nt][1], sc[nt][2], sc[nt][3],
                         a0, a1, a2, a3, b0, b1);
            }
        }

        // write scaled+masked S (fp32) to Ss
#pragma unroll
        for (int nt = 0; nt < 4; ++nt) {
            int cb = wn * 32 + nt * 8 + tig * 2;
            int kj = k0 + cb;
            int qi0 = q0 + wm * 16 + g;
            int qi1 = qi0 + 8;
            int rb = (wm * 16 + g) * AST + cb;
            Ss[rb]               = (kj     <= qi0) ? sc[nt][0] * 0.125f : NEG_INF;
            Ss[rb + 1]           = (kj + 1 <= qi0) ? sc[nt][1] * 0.125f : NEG_INF;
            Ss[rb + 8 * AST]     = (kj     <= qi1) ? sc[nt][2] * 0.125f : NEG_INF;
            Ss[rb + 8 * AST + 1] = (kj + 1 <= qi1) ? sc[nt][3] * 0.125f : NEG_INF;
        }
        __syncthreads();

        // online softmax: 4 threads per row, 16 cols each
        float vals[16];
        float mloc = NEG_INF;
#pragma unroll
        for (int c2 = 0; c2 < 16; ++c2) {
            vals[c2] = Ss[r_own * AST + c_own + c2];
            mloc = fmaxf(mloc, vals[c2]);
        }
        mloc = fmaxf(mloc, __shfl_xor_sync(0xffffffffu, mloc, 1));
        mloc = fmaxf(mloc, __shfl_xor_sync(0xffffffffu, mloc, 2));
        float m_new = fmaxf(m_prev, mloc);
        float alpha = __expf(m_prev - m_new);
        float ssum = 0.f;
#pragma unroll
        for (int c2 = 0; c2 < 16; ++c2) {
            float pv = __expf(vals[c2] - m_new);
            Ss[r_own * AST + c_own + c2] = __uint_as_float(f2tf32(pv));  // P as tf32 bits
            ssum += pv;
        }
        ssum += __shfl_xor_sync(0xffffffffu, ssum, 1);
        ssum += __shfl_xor_sync(0xffffffffu, ssum, 2);
        l_prev = l_prev * alpha + ssum;
        m_prev = m_new;
        if ((tid & 3) == 0) rowA[r_own] = alpha;
        __syncthreads();

        // O = O*alpha + P @ V
        float al0 = rowA[wm * 16 + g];
        float al1 = rowA[wm * 16 + g + 8];
#pragma unroll
        for (int nt = 0; nt < 4; ++nt) {
            o[nt][0] *= al0; o[nt][1] *= al0;
            o[nt][2] *= al1; o[nt][3] *= al1;
        }

        const uint32_t* Pu = (const uint32_t*)Ss;
#pragma unroll
        for (int kk0 = 0; kk0 < 64; kk0 += 8) {
            int pr = (wm * 16 + g) * AST;
            uint32_t a0 = Pu[pr + kk0 + tig];
            uint32_t a1 = Pu[pr + 8 * AST + kk0 + tig];
            uint32_t a2 = Pu[pr + kk0 + tig + 4];
            uint32_t a3 = Pu[pr + 8 * AST + kk0 + tig + 4];
#pragma unroll
            for (int nt = 0; nt < 4; ++nt) {
                int dr = (wn * 32 + nt * 8 + g) * AST;
                uint32_t b0 = Vt[dr + kk0 + tig];
                uint32_t b1 = Vt[dr + kk0 + tig + 4];
                mma_tf32(o[nt][0], o[nt][1], o[nt][2], o[nt][3],
                         a0, a1, a2, a3, b0, b1);
            }
        }
    }

    // normalize and write out in [B,T,C] layout
    __syncthreads();
    if ((tid & 3) == 0) rowA[r_own] = 1.f / l_prev;
    __syncthreads();
    {
        float inv0 = rowA[wm * 16 + g];
        float inv1 = rowA[wm * 16 + g + 8];
        int qrow0 = q0 + wm * 16 + g;
#pragma unroll
        for (int nt = 0; nt < 4; ++nt) {
            int d = wn * 32 + nt * 8 + tig * 2;
            float2 v;
            v.x = o[nt][0] * inv0;
            v.y = o[nt][1] * inv0;
            *(float2*)&O[(b * TT + qrow0) * CC + head * DD + d] = v;
            v.x = o[nt][2] * inv1;
            v.y = o[nt][3] * inv1;
            *(float2*)&O[(b * TT + qrow0 + 8) * CC + head * DD + d] = v;
        }
    }
}

// ---------------------------------------------------------------------------
extern "C" void kernel_launch(void* const* d_in, const int* in_sizes, int n_in,
                              void* d_out, int out_size)
{
    const float* x    = (const float*)d_in[0];  // [4,2048,1024]
    const float* Wqkv = (const float*)d_in[1];  // [1024,3072]
    const float* bqkv = (const float*)d_in[2];  // [3072]
    const float* Wo   = (const float*)d_in[3];  // [1024,1024]
    const float* bo   = (const float*)d_in[4];  // [1024]
    float* out = (float*)d_out;                 // [4,2048,1024]

    float *gQ, *gK, *gV, *gAtt;
    cudaGetSymbolAddress((void**)&gQ,   g_Q);
    cudaGetSymbolAddress((void**)&gK,   g_K);
    cudaGetSymbolAddress((void**)&gV,   g_V);
    cudaGetSymbolAddress((void**)&gAtt, g_Att);

    // 1) QKV projection + scatter to [B,H,T,D]
    gemm_tf32<<<dim3(3072 / 128, M_TOT / 128), 256>>>(
        x, Wqkv, bqkv, nullptr, gQ, gK, gV, 3072, 1);

    // 2) causal flash attention -> [B,T,C]
    cudaFuncSetAttribute(attn_tf32, cudaFuncAttributeMaxDynamicSharedMemorySize,
                         ATTN_SMEM_BYTES);
    attn_tf32<<<dim3(TT / 64, HH, BB), 256, ATTN_SMEM_BYTES>>>(gQ, gK, gV, gAtt);

    // 3) output projection
    gemm_tf32<<<dim3(1024 / 128, M_TOT / 128), 256>>>(
        gAtt, Wo, bo, out, nullptr, nullptr, nullptr, 1024, 0);
}

// round 4
// speedup vs baseline: 3.6557x; 1.4665x over previous
#include <cuda_runtime.h>
#include <cuda_fp16.h>
#include <cstdint>

#define BB 4
#define TT 2048
#define CC 1024
#define HH 16
#define DD 64
#define M_TOT (BB*TT)   // 8192

// Scratch (device globals: allocation-free rule)
__device__ float g_Q[BB*HH*TT*DD];    // [B,H,T,D]
__device__ float g_K[BB*HH*TT*DD];
__device__ float g_V[BB*HH*TT*DD];
__device__ float g_Att[BB*TT*CC];     // attention out in [B,T,C]

__device__ __forceinline__ uint32_t f2tf32(float x) {
    uint32_t y;
    asm("cvt.rna.tf32.f32 %0, %1;" : "=r"(y) : "f"(x));
    return y;
}

__device__ __forceinline__ void mma_tf32(float& c0, float& c1, float& c2, float& c3,
                                         uint32_t a0, uint32_t a1, uint32_t a2, uint32_t a3,
                                         uint32_t b0, uint32_t b1)
{
    asm volatile(
        "mma.sync.aligned.m16n8k8.row.col.f32.tf32.tf32.f32 "
        "{%0,%1,%2,%3}, {%4,%5,%6,%7}, {%8,%9}, {%0,%1,%2,%3};"
        : "+f"(c0), "+f"(c1), "+f"(c2), "+f"(c3)
        : "r"(a0), "r"(a1), "r"(a2), "r"(a3), "r"(b0), "r"(b1));
}

__device__ __forceinline__ void mma_f16(float& c0, float& c1, float& c2, float& c3,
                                        uint32_t a0, uint32_t a1, uint32_t a2, uint32_t a3,
                                        uint32_t b0, uint32_t b1)
{
    asm volatile(
        "mma.sync.aligned.m16n8k16.row.col.f32.f16.f16.f32 "
        "{%0,%1,%2,%3}, {%4,%5,%6,%7}, {%8,%9}, {%0,%1,%2,%3};"
        : "+f"(c0), "+f"(c1), "+f"(c2), "+f"(c3)
        : "r"(a0), "r"(a1), "r"(a2), "r"(a3), "r"(b0), "r"(b1));
}

__device__ __forceinline__ void cp_async16(void* smem_dst, const void* gmem_src) {
    uint32_t s = (uint32_t)__cvta_generic_to_shared(smem_dst);
    asm volatile("cp.async.cg.shared.global [%0], [%1], 16;" :: "r"(s), "l"(gmem_src));
}
#define CP_COMMIT() asm volatile("cp.async.commit_group;")
#define CP_WAIT1()  asm volatile("cp.async.wait_group 1;")

// ---------------------------------------------------------------------------
// tf32 GEMM with cp.async 2-stage pipeline.
// Out[M,N] = A[M,1024] @ W[1024,N] + bias[N]
// Tile 128x128x32, 256 threads (8 warps 4m x 2n), warp tile 32x64.
// Smem: As [2][128][36] f32 (row-major m,k), Bs [2][32][136] f32 (k,n)
// mode 0: row-major write; mode 1: QKV scatter to [B,H,T,D]
// ---------------------------------------------------------------------------
#define GA_ST 36
#define GB_ST 136
#define GA_FL (128*GA_ST)        // 4608 floats per A buffer
#define GB_FL (32*GB_ST)         // 4352 floats per B buffer
#define GEMM_SMEM_BYTES ((2*GA_FL + 2*GB_FL) * 4)   // 71680

__global__ __launch_bounds__(256, 2)
void gemm_tf32(const float* __restrict__ A, const float* __restrict__ W,
               const float* __restrict__ bias, float* __restrict__ Out,
               float* __restrict__ Qp, float* __restrict__ Kp, float* __restrict__ Vp,
               int N, int mode)
{
    extern __shared__ float sm[];
    float* Asm[2] = { sm,            sm + GA_FL };
    float* Bsm[2] = { sm + 2*GA_FL,  sm + 2*GA_FL + GB_FL };

    const int tid  = threadIdx.x;
    const int wid  = tid >> 5;
    const int lane = tid & 31;
    const int g    = lane >> 2;
    const int tig  = lane & 3;
    const int wm   = wid & 3;          // m offset wm*32
    const int wn   = wid >> 2;         // n offset wn*64
    const int n0   = blockIdx.x * 128;
    const int m0   = blockIdx.y * 128;

    float acc[2][8][4];
#pragma unroll
    for (int mt = 0; mt < 2; ++mt)
#pragma unroll
        for (int nt = 0; nt < 8; ++nt)
#pragma unroll
            for (int q = 0; q < 4; ++q) acc[mt][nt][q] = 0.f;

    // prefetch helper (4 A-chunks + 4 B-chunks of 16B per thread)
    auto prefetch = [&](int kt, int buf) {
        const int k0 = kt * 32;
#pragma unroll
        for (int p = 0; p < 4; ++p) {
            int c  = tid + p * 256;            // 0..1023
            int ra = c >> 3;                   // A row 0..127
            int ka = (c & 7) * 4;              // 0..28
            cp_async16(&Asm[buf][ra * GA_ST + ka], &A[(m0 + ra) * 1024 + k0 + ka]);
            int rb = c >> 5;                   // B k-row 0..31
            int nb = (c & 31) * 4;             // 0..124
            cp_async16(&Bsm[buf][rb * GB_ST + nb], &W[(k0 + rb) * N + n0 + nb]);
        }
    };

    prefetch(0, 0);
    CP_COMMIT();

    for (int kt = 0; kt < 32; ++kt) {
        if (kt + 1 < 32) prefetch(kt + 1, (kt + 1) & 1);
        CP_COMMIT();
        CP_WAIT1();
        __syncthreads();

        const float* As = Asm[kt & 1];
        const float* Bs = Bsm[kt & 1];

#pragma unroll
        for (int ks = 0; ks < 4; ++ks) {
            const int kk = ks * 8;
            uint32_t af[2][4];
#pragma unroll
            for (int mt = 0; mt < 2; ++mt) {
                int mr = (wm * 32 + mt * 16 + g) * GA_ST;
                af[mt][0] = f2tf32(As[mr + kk + tig]);
                af[mt][1] = f2tf32(As[mr + 8 * GA_ST + kk + tig]);
                af[mt][2] = f2tf32(As[mr + kk + tig + 4]);
                af[mt][3] = f2tf32(As[mr + 8 * GA_ST + kk + tig + 4]);
            }
#pragma unroll
            for (int nt = 0; nt < 8; ++nt) {
                int nc = wn * 64 + nt * 8 + g;
                uint32_t b0 = f2tf32(Bs[(kk + tig    ) * GB_ST + nc]);
                uint32_t b1 = f2tf32(Bs[(kk + tig + 4) * GB_ST + nc]);
#pragma unroll
                for (int mt = 0; mt < 2; ++mt)
                    mma_tf32(acc[mt][nt][0], acc[mt][nt][1], acc[mt][nt][2], acc[mt][nt][3],
                             af[mt][0], af[mt][1], af[mt][2], af[mt][3], b0, b1);
            }
        }
        __syncthreads();
    }

    // epilogue
#pragma unroll
    for (int mt = 0; mt < 2; ++mt) {
#pragma unroll
        for (int nt = 0; nt < 8; ++nt) {
            int col = n0 + wn * 64 + nt * 8 + tig * 2;
            float2 bv = *(const float2*)&bias[col];
            int r0 = m0 + wm * 32 + mt * 16 + g;
#pragma unroll
            for (int h = 0; h < 2; ++h) {
                int row = r0 + h * 8;
                float2 v;
                v.x = acc[mt][nt][h * 2 + 0] + bv.x;
                v.y = acc[mt][nt][h * 2 + 1] + bv.y;
                if (mode == 0) {
                    *(float2*)&Out[row * N + col] = v;
                } else {
                    int sec = col >> 10;           // 0:Q 1:K 2:V
                    int rem = col & 1023;
                    int hh  = rem >> 6;
                    int d   = rem & 63;
                    int b   = row >> 11;
                    int t   = row & 2047;
                    float* dst = (sec == 0) ? Qp : (sec == 1) ? Kp : Vp;
                    *(float2*)&dst[(((b * HH + hh) * TT + t) << 6) + d] = v;
                }
            }
        }
    }
}

// ---------------------------------------------------------------------------
// Flash attention: 128-row q-block, 8 warps (warp = 16 q rows x full tile).
// Q fragments held in registers (tf32, pre-scaled by 0.125).
// S via tf32 mma; in-register online softmax (quad shfl); P->fp16 in regs;
// P@V via fp16 m16n8k16 (V from f32 smem, cvt at fragment load).
// K/V tiles double-buffered via cp.async.
// ---------------------------------------------------------------------------
#define KV_ST 68
#define KV_FL (64*KV_ST)                       // 4352 floats per buffer
#define ATTN_SMEM_BYTES (4*KV_FL*4)            // 69632

__global__ __launch_bounds__(256, 2)
void attn_tf32(const float* __restrict__ Q, const float* __restrict__ K,
               const float* __restrict__ V, float* __restrict__ O)
{
    extern __shared__ float sm[];
    float* Kb[2] = { sm,            sm + KV_FL };
    float* Vb[2] = { sm + 2*KV_FL,  sm + 3*KV_FL };

    const float NEG_INF = -__int_as_float(0x7f800000);

    const int tid  = threadIdx.x;
    const int wid  = tid >> 5;
    const int lane = tid & 31;
    const int g    = lane >> 2;
    const int tig  = lane & 3;
    const int wq   = wid * 16;            // warp q offset within block
    const int qb   = blockIdx.x;          // q block (128 rows)
    const int head = blockIdx.y;
    const int b    = blockIdx.z;
    const int q0   = qb * 128;

    const int base = (b * HH + head) * TT * DD;
    const float* Qg = Q + base;
    const float* Kg = K + base;
    const float* Vg = V + base;

    // ---- stage Q through smem (once), build register fragments ----
    {
        float* Qs = sm;                    // 128 x KV_ST (fits in Kb0+Kb1)
#pragma unroll
        for (int p = 0; p < 8; ++p) {
            int idx = tid + p * 256;       // 0..2047 chunks of 4
            int r   = idx >> 4;
            int d0  = (idx & 15) * 4;
            *(float4*)&sm[r * KV_ST + d0] = *(const float4*)&Qg[(q0 + r) * DD + d0];
        }
        __syncthreads();
    }
    uint32_t qa[8][4];
    {
        const float* Qs = sm;
        const float scale = 0.125f;
        int r0 = (wq + g) * KV_ST;
        int r1 = (wq + g + 8) * KV_ST;
#pragma unroll
        for (int d8 = 0; d8 < 8; ++d8) {
            int d = d8 * 8;
            qa[d8][0] = f2tf32(Qs[r0 + d + tig] * scale);
            qa[d8][1] = f2tf32(Qs[r1 + d + tig] * scale);
            qa[d8][2] = f2tf32(Qs[r0 + d + tig + 4] * scale);
            qa[d8][3] = f2tf32(Qs[r1 + d + tig + 4] * scale);
        }
        __syncthreads();   // Q reads done before K/V cp.async overwrites
    }

    float o[8][4];
#pragma unroll
    for (int nt = 0; nt < 8; ++nt)
#pragma unroll
        for (int q = 0; q < 4; ++q) o[nt][q] = 0.f;

    float m0 = NEG_INF, m1 = NEG_INF, l0 = 0.f, l1 = 0.f;
    const int row0 = q0 + wq + g;
    const int row1 = row0 + 8;

    const int n_tiles = 2 * (qb + 1);

    auto prefetch = [&](int jt, int buf) {
        const int k0 = jt * 64;
#pragma unroll
        for (int p = 0; p < 4; ++p) {
            int c  = tid + p * 256;        // 0..1023
            int r  = c >> 4;
            int dc = (c & 15) * 4;
            cp_async16(&Kb[buf][r * KV_ST + dc], &Kg[(k0 + r) * DD + dc]);
            cp_async16(&Vb[buf][r * KV_ST + dc], &Vg[(k0 + r) * DD + dc]);
        }
    };

    prefetch(0, 0);
    CP_COMMIT();

    for (int jt = 0; jt < n_tiles; ++jt) {
        const int k0 = jt * 64;
        if (jt + 1 < n_tiles) prefetch(jt + 1, (jt + 1) & 1);
        CP_COMMIT();
        CP_WAIT1();
        __syncthreads();

        const float* Ks = Kb[jt & 1];
        const float* Vs = Vb[jt & 1];

        // ---- S = Q . K^T ----
        float sc[8][4];
#pragma unroll
        for (int nt = 0; nt < 8; ++nt)
#pragma unroll
            for (int q = 0; q < 4; ++q) sc[nt][q] = 0.f;

#pragma unroll
        for (int d8 = 0; d8 < 8; ++d8) {
            int d = d8 * 8;
#pragma unroll
            for (int nt = 0; nt < 8; ++nt) {
                int kr = (nt * 8 + g) * KV_ST;
                uint32_t b0 = f2tf32(Ks[kr + d + tig]);
                uint32_t b1 = f2tf32(Ks[kr + d + tig + 4]);
                mma_tf32(sc[nt][0], sc[nt][1], sc[nt][2], sc[nt][3],
                         qa[d8][0], qa[d8][1], qa[d8][2], qa[d8][3], b0, b1);
            }
        }

        // ---- causal mask (only tiles touching the diagonal for this warp) ----
        if (k0 + 63 > row0) {
#pragma unroll
            for (int nt = 0; nt < 8; ++nt) {
                int c0 = k0 + nt * 8 + tig * 2;
                int c1 = c0 + 1;
                if (c0 > row0) sc[nt][0] = NEG_INF;
                if (c1 > row0) sc[nt][1] = NEG_INF;
                if (c0 > row1) sc[nt][2] = NEG_INF;
                if (c1 > row1) sc[nt][3] = NEG_INF;
            }
        }

        // ---- in-register online softmax (rows g, g+8; reduce over quad) ----
        float mx0 = NEG_INF, mx1 = NEG_INF;
#pragma unroll
        for (int nt = 0; nt < 8; ++nt) {
            mx0 = fmaxf(mx0, fmaxf(sc[nt][0], sc[nt][1]));
            mx1 = fmaxf(mx1, fmaxf(sc[nt][2], sc[nt][3]));
        }
        mx0 = fmaxf(mx0, __shfl_xor_sync(0xffffffffu, mx0, 1));
        mx0 = fmaxf(mx0, __shfl_xor_sync(0xffffffffu, mx0, 2));
        mx1 = fmaxf(mx1, __shfl_xor_sync(0xffffffffu, mx1, 1));
        mx1 = fmaxf(mx1, __shfl_xor_sync(0xffffffffu, mx1, 2));

        float mn0 = fmaxf(m0, mx0);
        float mn1 = fmaxf(m1, mx1);
        float al0 = __expf(m0 - mn0);     // -inf - finite -> 0
        float al1 = __expf(m1 - mn1);
        m0 = mn0; m1 = mn1;

        uint32_t ph[8][2];                // P as half2 pairs
        float s0 = 0.f, s1 = 0.f;
#pragma unroll
        for (int nt = 0; nt < 8; ++nt) {
            float p0 = __expf(sc[nt][0] - m0);
            float p1 = __expf(sc[nt][1] - m0);
            float p2 = __expf(sc[nt][2] - m1);
            float p3 = __expf(sc[nt][3] - m1);
            s0 += p0 + p1;
            s1 += p2 + p3;
            __half2 h01 = __floats2half2_rn(p0, p1);
            __half2 h23 = __floats2half2_rn(p2, p3);
            ph[nt][0] = *(uint32_t*)&h01;
            ph[nt][1] = *(uint32_t*)&h23;
        }
        s0 += __shfl_xor_sync(0xffffffffu, s0, 1);
        s0 += __shfl_xor_sync(0xffffffffu, s0, 2);
        s1 += __shfl_xor_sync(0xffffffffu, s1, 1);
        s1 += __shfl_xor_sync(0xffffffffu, s1, 2);
        l0 = l0 * al0 + s0;
        l1 = l1 * al1 + s1;

        // ---- rescale O ----
#pragma unroll
        for (int nt = 0; nt < 8; ++nt) {
            o[nt][0] *= al0; o[nt][1] *= al0;
            o[nt][2] *= al1; o[nt][3] *= al1;
        }

        // ---- O += P @ V  (fp16 mma, V cvt at fragment load) ----
#pragma unroll
        for (int c = 0; c < 4; ++c) {      // k16 chunks over 64 keys
            uint32_t a0 = ph[2*c    ][0];
            uint32_t a1 = ph[2*c    ][1];
            uint32_t a2 = ph[2*c + 1][0];
            uint32_t a3 = ph[2*c + 1][1];
            int kr0 = (c * 16 + tig * 2) * KV_ST;
            int kr1 = kr0 + 8 * KV_ST;
#pragma unroll
            for (int nt = 0; nt < 8; ++nt) {
                int dcol = nt * 8 + g;
                __half2 v0 = __floats2half2_rn(Vs[kr0 + dcol], Vs[kr0 + KV_ST + dcol]);
                __half2 v1 = __floats2half2_rn(Vs[kr1 + dcol], Vs[kr1 + KV_ST + dcol]);
                mma_f16(o[nt][0], o[nt][1], o[nt][2], o[nt][3],
                        a0, a1, a2, a3, *(uint32_t*)&v0, *(uint32_t*)&v1);
            }
        }
        __syncthreads();   // all reads of this buffer done before reuse
    }

    // ---- normalize, write [B,T,C] ----
    float inv0 = 1.f / l0;
    float inv1 = 1.f / l1;
#pragma unroll
    for (int nt = 0; nt < 8; ++nt) {
        int d = head * DD + nt * 8 + tig * 2;
        float2 v;
        v.x = o[nt][0] * inv0;
        v.y = o[nt][1] * inv0;
        *(float2*)&O[(b * TT + row0) * CC + d] = v;
        v.x = o[nt][2] * inv1;
        v.y = o[nt][3] * inv1;
        *(float2*)&O[(b * TT + row1) * CC + d] = v;
    }
}

// ---------------------------------------------------------------------------
extern "C" void kernel_launch(void* const* d_in, const int* in_sizes, int n_in,
                              void* d_out, int out_size)
{
    const float* x    = (const float*)d_in[0];  // [4,2048,1024]
    const float* Wqkv = (const float*)d_in[1];  // [1024,3072]
    const float* bqkv = (const float*)d_in[2];  // [3072]
    const float* Wo   = (const float*)d_in[3];  // [1024,1024]
    const float* bo   = (const float*)d_in[4];  // [1024]
    float* out = (float*)d_out;                 // [4,2048,1024]

    float *gQ, *gK, *gV, *gAtt;
    cudaGetSymbolAddress((void**)&gQ,   g_Q);
    cudaGetSymbolAddress((void**)&gK,   g_K);
    cudaGetSymbolAddress((void**)&gV,   g_V);
    cudaGetSymbolAddress((void**)&gAtt, g_Att);

    cudaFuncSetAttribute(gemm_tf32, cudaFuncAttributeMaxDynamicSharedMemorySize,
                         GEMM_SMEM_BYTES);
    cudaFuncSetAttribute(attn_tf32, cudaFuncAttributeMaxDynamicSharedMemorySize,
                         ATTN_SMEM_BYTES);

    // 1) QKV projection + scatter to [B,H,T,D]
    gemm_tf32<<<dim3(3072 / 128, M_TOT / 128), 256, GEMM_SMEM_BYTES>>>(
        x, Wqkv, bqkv, nullptr, gQ, gK, gV, 3072, 1);

    // 2) causal flash attention -> [B,T,C]
    attn_tf32<<<dim3(TT / 128, HH, BB), 256, ATTN_SMEM_BYTES>>>(gQ, gK, gV, gAtt);

    // 3) output projection
    gemm_tf32<<<dim3(1024 / 128, M_TOT / 128), 256, GEMM_SMEM_BYTES>>>(
        gAtt, Wo, bo, out, nullptr, nullptr, nullptr, 1024, 0);
}

// round 5
// speedup vs baseline: 8.0069x; 2.1902x over previous
#include <cuda_runtime.h>
#include <cuda_fp16.h>
#include <cstdint>

#define BB 4
#define TT 2048
#define CC 1024
#define HH 16
#define DD 64
#define M_TOT (BB*TT)   // 8192

// Scratch (device globals: allocation-free rule)
__device__ __half g_xh[M_TOT*CC];        // x in fp16
__device__ __half g_wqkvh[CC*3*CC];      // W_qkv in fp16
__device__ __half g_woh[CC*CC];          // W_o in fp16
__device__ __half g_Q[BB*HH*TT*DD];      // [B,H,T,D] fp16 (pre-scale NOT applied)
__device__ __half g_K[BB*HH*TT*DD];
__device__ __half g_V[BB*HH*TT*DD];
__device__ __half g_Att[M_TOT*CC];       // attention out [B,T,C] fp16

__device__ __forceinline__ void mma_f16(float& c0, float& c1, float& c2, float& c3,
                                        uint32_t a0, uint32_t a1, uint32_t a2, uint32_t a3,
                                        uint32_t b0, uint32_t b1)
{
    asm volatile(
        "mma.sync.aligned.m16n8k16.row.col.f32.f16.f16.f32 "
        "{%0,%1,%2,%3}, {%4,%5,%6,%7}, {%8,%9}, {%0,%1,%2,%3};"
        : "+f"(c0), "+f"(c1), "+f"(c2), "+f"(c3)
        : "r"(a0), "r"(a1), "r"(a2), "r"(a3), "r"(b0), "r"(b1));
}

__device__ __forceinline__ void ldsm_x4(uint32_t& r0, uint32_t& r1, uint32_t& r2, uint32_t& r3,
                                        uint32_t addr)
{
    asm volatile("ldmatrix.sync.aligned.m8n8.x4.shared.b16 {%0,%1,%2,%3}, [%4];"
                 : "=r"(r0), "=r"(r1), "=r"(r2), "=r"(r3) : "r"(addr));
}

__device__ __forceinline__ void ldsm_x4_t(uint32_t& r0, uint32_t& r1, uint32_t& r2, uint32_t& r3,
                                          uint32_t addr)
{
    asm volatile("ldmatrix.sync.aligned.m8n8.x4.trans.shared.b16 {%0,%1,%2,%3}, [%4];"
                 : "=r"(r0), "=r"(r1), "=r"(r2), "=r"(r3) : "r"(addr));
}

__device__ __forceinline__ void cp_async16(void* smem_dst, const void* gmem_src) {
    uint32_t s = (uint32_t)__cvta_generic_to_shared(smem_dst);
    asm volatile("cp.async.cg.shared.global [%0], [%1], 16;" :: "r"(s), "l"(gmem_src));
}
#define CP_COMMIT() asm volatile("cp.async.commit_group;")
#define CP_WAIT1()  asm volatile("cp.async.wait_group 1;")

// ---------------------------------------------------------------------------
// fp32 -> fp16 conversion (one-time preprocess)
// ---------------------------------------------------------------------------
__global__ void cvt_half_kernel(const float* __restrict__ src, __half* __restrict__ dst, int n)
{
    int i = (blockIdx.x * blockDim.x + threadIdx.x) * 4;
    if (i < n) {
        float4 v = *(const float4*)&src[i];
        __half2 h0 = __floats2half2_rn(v.x, v.y);
        __half2 h1 = __floats2half2_rn(v.z, v.w);
        *(__half2*)&dst[i]     = h0;
        *(__half2*)&dst[i + 2] = h1;
    }
}

// ---------------------------------------------------------------------------
// fp16 GEMM with cp.async 2-stage pipeline + ldmatrix fragments.
// Out[M,N] = A[M,1024] @ W[1024,N] + bias[N]  (A,W fp16; acc fp32)
// Tile 128x128x32, 256 threads (8 warps 4m x 2n), warp tile 32x64.
// Smem: As [2][128][40] half (row-major m,k), Bs [2][32][136] half (k,n)
// mode 0: fp32 row-major write; mode 1: QKV fp16 scatter to [B,H,T,D]
// ---------------------------------------------------------------------------
#define GA_STH 40
#define GB_STH 136
#define GA_H (128*GA_STH)        // 5120 halves / buffer
#define GB_H (32*GB_STH)         // 4352 halves / buffer
#define GEMM_SMEM_BYTES ((2*GA_H + 2*GB_H) * 2)   // 37888

__global__ __launch_bounds__(256, 2)
void gemm_f16(const __half* __restrict__ A, const __half* __restrict__ W,
              const float* __restrict__ bias, float* __restrict__ Out,
              __half* __restrict__ Qp, __half* __restrict__ Kp, __half* __restrict__ Vp,
              int N, int mode)
{
    extern __shared__ __half smh[];
    __half* Asm[2] = { smh,           smh + GA_H };
    __half* Bsm[2] = { smh + 2*GA_H,  smh + 2*GA_H + GB_H };

    const int tid  = threadIdx.x;
    const int wid  = tid >> 5;
    const int lane = tid & 31;
    const int g    = lane >> 2;
    const int tig  = lane & 3;
    const int lr   = lane & 7;
    const int sel  = lane >> 3;
    const int wm   = wid & 3;          // m offset wm*32
    const int wn   = wid >> 2;         // n offset wn*64
    const int n0   = blockIdx.x * 128;
    const int m0   = blockIdx.y * 128;

    // ldmatrix per-lane byte offsets
    const uint32_t smA[2] = { (uint32_t)__cvta_generic_to_shared(Asm[0]),
                              (uint32_t)__cvta_generic_to_shared(Asm[1]) };
    const uint32_t smB[2] = { (uint32_t)__cvta_generic_to_shared(Bsm[0]),
                              (uint32_t)__cvta_generic_to_shared(Bsm[1]) };
    const uint32_t aOff = ((wm * 32 + (sel & 1) * 8 + lr) * GA_STH + (sel >> 1) * 8) * 2;
    const uint32_t bOff = (((sel & 1) * 8 + lr) * GB_STH + wn * 64 + (sel >> 1) * 8) * 2;

    float acc[2][8][4];
#pragma unroll
    for (int mt = 0; mt < 2; ++mt)
#pragma unroll
        for (int nt = 0; nt < 8; ++nt)
#pragma unroll
            for (int q = 0; q < 4; ++q) acc[mt][nt][q] = 0.f;

    // prefetch: A 512 chunks (128 rows x 4), B 512 chunks (32 rows x 16); 16B each
    auto prefetch = [&](int kt, int buf) {
        const int k0 = kt * 32;
#pragma unroll
        for (int p = 0; p < 2; ++p) {
            int c  = tid + p * 256;            // 0..511
            int ra = c >> 2;                   // A row 0..127
            int ka = (c & 3) * 8;              // halves 0,8,16,24
            cp_async16(&Asm[buf][ra * GA_STH + ka], &A[(m0 + ra) * 1024 + k0 + ka]);
            int rb = c >> 4;                   // B k-row 0..31
            int nb = (c & 15) * 8;             // halves 0..120
            cp_async16(&Bsm[buf][rb * GB_STH + nb], &W[(k0 + rb) * N + n0 + nb]);
        }
    };

    prefetch(0, 0);
    CP_COMMIT();

    for (int kt = 0; kt < 32; ++kt) {
        if (kt + 1 < 32) prefetch(kt + 1, (kt + 1) & 1);
        CP_COMMIT();
        CP_WAIT1();
        __syncthreads();

        const int buf = kt & 1;
#pragma unroll
        for (int ks = 0; ks < 2; ++ks) {
            uint32_t a[2][4];
#pragma unroll
            for (int mt = 0; mt < 2; ++mt)
                ldsm_x4(a[mt][0], a[mt][1], a[mt][2], a[mt][3],
                        smA[buf] + aOff + (mt * 16 * GA_STH + ks * 16) * 2);
#pragma unroll
            for (int p = 0; p < 4; ++p) {
                uint32_t b0a, b1a, b0b, b1b;
                ldsm_x4_t(b0a, b1a, b0b, b1b,
                          smB[buf] + bOff + (ks * 16 * GB_STH + p * 16) * 2);
#pragma unroll
                for (int mt = 0; mt < 2; ++mt) {
                    mma_f16(acc[mt][2*p][0], acc[mt][2*p][1], acc[mt][2*p][2], acc[mt][2*p][3],
                            a[mt][0], a[mt][1], a[mt][2], a[mt][3], b0a, b1a);
                    mma_f16(acc[mt][2*p+1][0], acc[mt][2*p+1][1], acc[mt][2*p+1][2], acc[mt][2*p+1][3],
                            a[mt][0], a[mt][1], a[mt][2], a[mt][3], b0b, b1b);
                }
            }
        }
        __syncthreads();
    }

    // epilogue: per (mt,nt): c0,c1 at (row g, cols 2tig,2tig+1), c2,c3 at row g+8
#pragma unroll
    for (int mt = 0; mt < 2; ++mt) {
#pragma unroll
        for (int nt = 0; nt < 8; ++nt) {
            int col = n0 + wn * 64 + nt * 8 + tig * 2;
            float2 bv = *(const float2*)&bias[col];
            int r0 = m0 + wm * 32 + mt * 16 + g;
#pragma unroll
            for (int h = 0; h < 2; ++h) {
                int row = r0 + h * 8;
                float vx = acc[mt][nt][h * 2 + 0] + bv.x;
                float vy = acc[mt][nt][h * 2 + 1] + bv.y;
                if (mode == 0) {
                    float2 v; v.x = vx; v.y = vy;
                    *(float2*)&Out[row * N + col] = v;
                } else {
                    int sec = col >> 10;           // 0:Q 1:K 2:V
                    int rem = col & 1023;
                    int hh  = rem >> 6;
                    int d   = rem & 63;
                    int b   = row >> 11;
                    int t   = row & 2047;
                    __half* dst = (sec == 0) ? Qp : (sec == 1) ? Kp : Vp;
                    *(__half2*)&dst[(((b * HH + hh) * TT + t) << 6) + d] =
                        __floats2half2_rn(vx, vy);
                }
            }
        }
    }
}

// ---------------------------------------------------------------------------
// Flash attention, all fp16 operands (fp32 softmax/accum).
// 128-row q block, 8 warps (warp = 16 q rows x full 64-col tile).
// Q frags in regs (pre-scaled 0.125, exact). K via non-trans ldmatrix,
// V via trans ldmatrix. K/V double-buffered cp.async. Output fp16.
// ---------------------------------------------------------------------------
#define KV_STH 72
#define KV_H (64*KV_STH)                        // 4608 halves / buffer
#define ATTN_SMEM_BYTES (4*KV_H*2)              // 36864

__global__ __launch_bounds__(256, 2)
void attn_f16(const __half* __restrict__ Q, const __half* __restrict__ K,
              const __half* __restrict__ V, __half* __restrict__ O)
{
    extern __shared__ __half smh[];
    __half* Kb[2] = { smh,           smh + KV_H };
    __half* Vb[2] = { smh + 2*KV_H,  smh + 3*KV_H };

    const float NEG_INF = -__int_as_float(0x7f800000);

    const int tid  = threadIdx.x;
    const int wid  = tid >> 5;
    const int lane = tid & 31;
    const int g    = lane >> 2;
    const int tig  = lane & 3;
    const int lr   = lane & 7;
    const int sel  = lane >> 3;
    const int wq   = wid * 16;
    const int qb   = blockIdx.x;
    const int head = blockIdx.y;
    const int b    = blockIdx.z;
    const int q0   = qb * 128;

    const int base = (b * HH + head) * TT * DD;
    const __half* Qg = Q + base;
    const __half* Kg = K + base;
    const __half* Vg = V + base;

    const uint32_t smK[2] = { (uint32_t)__cvta_generic_to_shared(Kb[0]),
                              (uint32_t)__cvta_generic_to_shared(Kb[1]) };
    const uint32_t smV[2] = { (uint32_t)__cvta_generic_to_shared(Vb[0]),
                              (uint32_t)__cvta_generic_to_shared(Vb[1]) };
    // K (S's B-operand, non-trans): token=(sel>>1)*8+lr (+p*16), d=(sel&1)*8 (+ks*16)
    const uint32_t kOff = (((sel >> 1) * 8 + lr) * KV_STH + (sel & 1) * 8) * 2;
    // V (PV's B-operand, trans): token=(sel&1)*8+lr (+c*16), d=(sel>>1)*8 (+p*16)
    const uint32_t vOff = (((sel & 1) * 8 + lr) * KV_STH + (sel >> 1) * 8) * 2;
    // Q frags: row=wq+(sel&1)*8+lr, k=(sel>>1)*8 (+ks*16)
    const uint32_t qOff = ((wq + (sel & 1) * 8 + lr) * KV_STH + (sel >> 1) * 8) * 2;

    // ---- stage Q (scaled by 0.125) into smem, extract fragments ----
    {
        const __half2 sc2 = __float2half2_rn(0.125f);
#pragma unroll
        for (int p = 0; p < 16; ++p) {
            int idx = tid + p * 256;           // 0..4095 half2 chunks
            int r   = idx >> 5;                // 0..127
            int d2  = (idx & 31);              // half2 col 0..31
            __half2 v = *(const __half2*)&Qg[(q0 + r) * DD + d2 * 2];
            *(__half2*)&smh[r * KV_STH + d2 * 2] = __hmul2(v, sc2);
        }
        __syncthreads();
    }
    uint32_t qa[4][4];
    {
        uint32_t qBase = (uint32_t)__cvta_generic_to_shared(smh);
#pragma unroll
        for (int ks = 0; ks < 4; ++ks)
            ldsm_x4(qa[ks][0], qa[ks][1], qa[ks][2], qa[ks][3],
                    qBase + qOff + ks * 32);   // ks*16 halves
        __syncthreads();   // Q reads done before K/V cp.async overwrites
    }

    float o[8][4];
#pragma unroll
    for (int nt = 0; nt < 8; ++nt)
#pragma unroll
        for (int q = 0; q < 4; ++q) o[nt][q] = 0.f;

    float m0 = NEG_INF, m1 = NEG_INF, l0 = 0.f, l1 = 0.f;
    const int row0 = q0 + wq + g;
    const int row1 = row0 + 8;

    const int n_tiles = 2 * (qb + 1);

    auto prefetch = [&](int jt, int buf) {
        const int k0 = jt * 64;
#pragma unroll
        for (int p = 0; p < 2; ++p) {
            int c  = tid + p * 256;            // 0..511
            int r  = c >> 3;                   // 0..63
            int dc = (c & 7) * 8;              // halves
            cp_async16(&Kb[buf][r * KV_STH + dc], &Kg[(k0 + r) * DD + dc]);
            cp_async16(&Vb[buf][r * KV_STH + dc], &Vg[(k0 + r) * DD + dc]);
        }
    };

    prefetch(0, 0);
    CP_COMMIT();

    for (int jt = 0; jt < n_tiles; ++jt) {
        const int k0 = jt * 64;
        if (jt + 1 < n_tiles) prefetch(jt + 1, (jt + 1) & 1);
        CP_COMMIT();
        CP_WAIT1();
        __syncthreads();

        const int buf = jt & 1;

        // ---- S = Q . K^T ----
        float sc[8][4];
#pragma unroll
        for (int nt = 0; nt < 8; ++nt)
#pragma unroll
            for (int q = 0; q < 4; ++q) sc[nt][q] = 0.f;

#pragma unroll
        for (int ks = 0; ks < 4; ++ks) {
#pragma unroll
            for (int p = 0; p < 4; ++p) {
                uint32_t b0a, b1a, b0b, b1b;
                ldsm_x4(b0a, b1a, b0b, b1b,
                        smK[buf] + kOff + (p * 16 * KV_STH + ks * 16) * 2);
                mma_f16(sc[2*p][0], sc[2*p][1], sc[2*p][2], sc[2*p][3],
                        qa[ks][0], qa[ks][1], qa[ks][2], qa[ks][3], b0a, b1a);
                mma_f16(sc[2*p+1][0], sc[2*p+1][1], sc[2*p+1][2], sc[2*p+1][3],
                        qa[ks][0], qa[ks][1], qa[ks][2], qa[ks][3], b0b, b1b);
            }
        }

        // ---- causal mask ----
        if (k0 + 63 > row0) {
#pragma unroll
            for (int nt = 0; nt < 8; ++nt) {
                int c0 = k0 + nt * 8 + tig * 2;
                int c1 = c0 + 1;
                if (c0 > row0) sc[nt][0] = NEG_INF;
                if (c1 > row0) sc[nt][1] = NEG_INF;
                if (c0 > row1) sc[nt][2] = NEG_INF;
                if (c1 > row1) sc[nt][3] = NEG_INF;
            }
        }

        // ---- in-register online softmax ----
        float mx0 = NEG_INF, mx1 = NEG_INF;
#pragma unroll
        for (int nt = 0; nt < 8; ++nt) {
            mx0 = fmaxf(mx0, fmaxf(sc[nt][0], sc[nt][1]));
            mx1 = fmaxf(mx1, fmaxf(sc[nt][2], sc[nt][3]));
        }
        mx0 = fmaxf(mx0, __shfl_xor_sync(0xffffffffu, mx0, 1));
        mx0 = fmaxf(mx0, __shfl_xor_sync(0xffffffffu, mx0, 2));
        mx1 = fmaxf(mx1, __shfl_xor_sync(0xffffffffu, mx1, 1));
        mx1 = fmaxf(mx1, __shfl_xor_sync(0xffffffffu, mx1, 2));

        float mn0 = fmaxf(m0, mx0);
        float mn1 = fmaxf(m1, mx1);
        float al0 = __expf(m0 - mn0);
        float al1 = __expf(m1 - mn1);
        m0 = mn0; m1 = mn1;

        uint32_t ph[8][2];
        float s0 = 0.f, s1 = 0.f;
#pragma unroll
        for (int nt = 0; nt < 8; ++nt) {
            float p0 = __expf(sc[nt][0] - m0);
            float p1 = __expf(sc[nt][1] - m0);
            float p2 = __expf(sc[nt][2] - m1);
            float p3 = __expf(sc[nt][3] - m1);
            s0 += p0 + p1;
            s1 += p2 + p3;
            __half2 h01 = __floats2half2_rn(p0, p1);
            __half2 h23 = __floats2half2_rn(p2, p3);
            ph[nt][0] = *(uint32_t*)&h01;
            ph[nt][1] = *(uint32_t*)&h23;
        }
        s0 += __shfl_xor_sync(0xffffffffu, s0, 1);
        s0 += __shfl_xor_sync(0xffffffffu, s0, 2);
        s1 += __shfl_xor_sync(0xffffffffu, s1, 1);
        s1 += __shfl_xor_sync(0xffffffffu, s1, 2);
        l0 = l0 * al0 + s0;
        l1 = l1 * al1 + s1;

#pragma unroll
        for (int nt = 0; nt < 8; ++nt) {
            o[nt][0] *= al0; o[nt][1] *= al0;
            o[nt][2] *= al1; o[nt][3] *= al1;
        }

        // ---- O += P @ V ----
#pragma unroll
        for (int c = 0; c < 4; ++c) {      // k16 token chunks
            uint32_t a0 = ph[2*c    ][0];
            uint32_t a1 = ph[2*c    ][1];
            uint32_t a2 = ph[2*c + 1][0];
            uint32_t a3 = ph[2*c + 1][1];
#pragma unroll
            for (int p = 0; p < 4; ++p) {  // d 16-col pairs
                uint32_t b0a, b1a, b0b, b1b;
                ldsm_x4_t(b0a, b1a, b0b, b1b,
                          smV[buf] + vOff + (c * 16 * KV_STH + p * 16) * 2);
                mma_f16(o[2*p][0], o[2*p][1], o[2*p][2], o[2*p][3],
                        a0, a1, a2, a3, b0a, b1a);
                mma_f16(o[2*p+1][0], o[2*p+1][1], o[2*p+1][2], o[2*p+1][3],
                        a0, a1, a2, a3, b0b, b1b);
            }
        }
        __syncthreads();   // buffer reads done before reuse
    }

    // ---- normalize, write fp16 [B,T,C] ----
    float inv0 = 1.f / l0;
    float inv1 = 1.f / l1;
#pragma unroll
    for (int nt = 0; nt < 8; ++nt) {
        int d = head * DD + nt * 8 + tig * 2;
        *(__half2*)&O[(b * TT + row0) * CC + d] =
            __floats2half2_rn(o[nt][0] * inv0, o[nt][1] * inv0);
        *(__half2*)&O[(b * TT + row1) * CC + d] =
            __floats2half2_rn(o[nt][2] * inv1, o[nt][3] * inv1);
    }
}

// ---------------------------------------------------------------------------
extern "C" void kernel_launch(void* const* d_in, const int* in_sizes, int n_in,
                              void* d_out, int out_size)
{
    const float* x    = (const float*)d_in[0];  // [4,2048,1024]
    const float* Wqkv = (const float*)d_in[1];  // [1024,3072]
    const float* bqkv = (const float*)d_in[2];  // [3072]
    const float* Wo   = (const float*)d_in[3];  // [1024,1024]
    const float* bo   = (const float*)d_in[4];  // [1024]
    float* out = (float*)d_out;                 // [4,2048,1024]

    __half *xh, *wqkvh, *woh, *gQ, *gK, *gV, *gAtt;
    cudaGetSymbolAddress((void**)&xh,    g_xh);
    cudaGetSymbolAddress((void**)&wqkvh, g_wqkvh);
    cudaGetSymbolAddress((void**)&woh,   g_woh);
    cudaGetSymbolAddress((void**)&gQ,    g_Q);
    cudaGetSymbolAddress((void**)&gK,    g_K);
    cudaGetSymbolAddress((void**)&gV,    g_V);
    cudaGetSymbolAddress((void**)&gAtt,  g_Att);

    cudaFuncSetAttribute(gemm_f16, cudaFuncAttributeMaxDynamicSharedMemorySize,
                         GEMM_SMEM_BYTES);
    cudaFuncSetAttribute(attn_f16, cudaFuncAttributeMaxDynamicSharedMemorySize,
                         ATTN_SMEM_BYTES);

    // 0) convert inputs to fp16
    cvt_half_kernel<<<(M_TOT*CC/4 + 255)/256, 256>>>(x, xh, M_TOT*CC);
    cvt_half_kernel<<<(CC*3*CC/4 + 255)/256, 256>>>(Wqkv, wqkvh, CC*3*CC);
    cvt_half_kernel<<<(CC*CC/4 + 255)/256, 256>>>(Wo, woh, CC*CC);

    // 1) QKV projection + fp16 scatter to [B,H,T,D]
    gemm_f16<<<dim3(3072 / 128, M_TOT / 128), 256, GEMM_SMEM_BYTES>>>(
        xh, wqkvh, bqkv, nullptr, gQ, gK, gV, 3072, 1);

    // 2) causal flash attention -> fp16 [B,T,C]
    attn_f16<<<dim3(TT / 128, HH, BB), 256, ATTN_SMEM_BYTES>>>(gQ, gK, gV, gAtt);

    // 3) output projection (fp16 in, fp32 out)
    gemm_f16<<<dim3(1024 / 128, M_TOT / 128), 256, GEMM_SMEM_BYTES>>>(
        gAtt, woh, bo, out, nullptr, nullptr, nullptr, 1024, 0);
}

// round 6
// speedup vs baseline: 8.2148x; 1.0260x over previous
#include <cuda_runtime.h>
#include <cuda_fp16.h>
#include <cstdint>

#define BB 4
#define TT 2048
#define CC 1024
#define HH 16
#define DD 64
#define M_TOT (BB*TT)   // 8192

// Scratch (device globals: allocation-free rule)
__device__ __half g_xh[M_TOT*CC];        // x in fp16
__device__ __half g_wqkvh[CC*3*CC];      // W_qkv in fp16
__device__ __half g_woh[CC*CC];          // W_o in fp16
__device__ __half g_Q[BB*HH*TT*DD];      // [B,H,T,D] fp16
__device__ __half g_K[BB*HH*TT*DD];
__device__ __half g_V[BB*HH*TT*DD];
__device__ __half g_Att[M_TOT*CC];       // attention out [B,T,C] fp16

__device__ __forceinline__ void mma_f16(float& c0, float& c1, float& c2, float& c3,
                                        uint32_t a0, uint32_t a1, uint32_t a2, uint32_t a3,
                                        uint32_t b0, uint32_t b1)
{
    asm volatile(
        "mma.sync.aligned.m16n8k16.row.col.f32.f16.f16.f32 "
        "{%0,%1,%2,%3}, {%4,%5,%6,%7}, {%8,%9}, {%0,%1,%2,%3};"
        : "+f"(c0), "+f"(c1), "+f"(c2), "+f"(c3)
        : "r"(a0), "r"(a1), "r"(a2), "r"(a3), "r"(b0), "r"(b1));
}

__device__ __forceinline__ void ldsm_x4(uint32_t& r0, uint32_t& r1, uint32_t& r2, uint32_t& r3,
                                        uint32_t addr)
{
    asm volatile("ldmatrix.sync.aligned.m8n8.x4.shared.b16 {%0,%1,%2,%3}, [%4];"
                 : "=r"(r0), "=r"(r1), "=r"(r2), "=r"(r3) : "r"(addr));
}

__device__ __forceinline__ void ldsm_x4_t(uint32_t& r0, uint32_t& r1, uint32_t& r2, uint32_t& r3,
                                          uint32_t addr)
{
    asm volatile("ldmatrix.sync.aligned.m8n8.x4.trans.shared.b16 {%0,%1,%2,%3}, [%4];"
                 : "=r"(r0), "=r"(r1), "=r"(r2), "=r"(r3) : "r"(addr));
}

__device__ __forceinline__ void cp_async16(void* smem_dst, const void* gmem_src) {
    uint32_t s = (uint32_t)__cvta_generic_to_shared(smem_dst);
    asm volatile("cp.async.cg.shared.global [%0], [%1], 16;" :: "r"(s), "l"(gmem_src));
}
#define CP_COMMIT() asm volatile("cp.async.commit_group;")
#define CP_WAIT1()  asm volatile("cp.async.wait_group 1;")
#define CP_WAIT0()  asm volatile("cp.async.wait_all;")

// ---------------------------------------------------------------------------
// fp32 -> fp16 conversion (one-time preprocess)
// ---------------------------------------------------------------------------
__global__ void cvt_half_kernel(const float* __restrict__ src, __half* __restrict__ dst, int n)
{
    int i = (blockIdx.x * blockDim.x + threadIdx.x) * 4;
    if (i < n) {
        float4 v = *(const float4*)&src[i];
        *(__half2*)&dst[i]     = __floats2half2_rn(v.x, v.y);
        *(__half2*)&dst[i + 2] = __floats2half2_rn(v.z, v.w);
    }
}

// ---------------------------------------------------------------------------
// fp16 GEMM, cp.async 2-stage pipeline, K-tile = 64 (16 iterations).
// Out[M,N] = A[M,1024] @ W[1024,N] + bias[N]  (A,W fp16; acc fp32)
// Tile 128x128x64, 256 threads (8 warps 4m x 2n), warp tile 32x64.
// Smem: As [2][128][72] half, Bs [2][64][136] half.
// mode 0: fp32 row-major write; mode 1: QKV fp16 scatter to [B,H,T,D]
// ---------------------------------------------------------------------------
#define GA_STH 72
#define GB_STH 136
#define GA_H (128*GA_STH)        // 9216 halves / buffer
#define GB_H (64*GB_STH)         // 8704 halves / buffer
#define GEMM_SMEM_BYTES ((2*GA_H + 2*GB_H) * 2)   // 71680

__global__ __launch_bounds__(256, 2)
void gemm_f16(const __half* __restrict__ A, const __half* __restrict__ W,
              const float* __restrict__ bias, float* __restrict__ Out,
              __half* __restrict__ Qp, __half* __restrict__ Kp, __half* __restrict__ Vp,
              int N, int mode)
{
    extern __shared__ __half smh[];
    __half* Asm[2] = { smh,           smh + GA_H };
    __half* Bsm[2] = { smh + 2*GA_H,  smh + 2*GA_H + GB_H };

    const int tid  = threadIdx.x;
    const int wid  = tid >> 5;
    const int lane = tid & 31;
    const int g    = lane >> 2;
    const int tig  = lane & 3;
    const int lr   = lane & 7;
    const int sel  = lane >> 3;
    const int wm   = wid & 3;          // m offset wm*32
    const int wn   = wid >> 2;         // n offset wn*64
    const int n0   = blockIdx.x * 128;
    const int m0   = blockIdx.y * 128;

    const uint32_t smA[2] = { (uint32_t)__cvta_generic_to_shared(Asm[0]),
                              (uint32_t)__cvta_generic_to_shared(Asm[1]) };
    const uint32_t smB[2] = { (uint32_t)__cvta_generic_to_shared(Bsm[0]),
                              (uint32_t)__cvta_generic_to_shared(Bsm[1]) };
    const uint32_t aOff = ((wm * 32 + (sel & 1) * 8 + lr) * GA_STH + (sel >> 1) * 8) * 2;
    const uint32_t bOff = (((sel & 1) * 8 + lr) * GB_STH + wn * 64 + (sel >> 1) * 8) * 2;

    float acc[2][8][4];
#pragma unroll
    for (int mt = 0; mt < 2; ++mt)
#pragma unroll
        for (int nt = 0; nt < 8; ++nt)
#pragma unroll
            for (int q = 0; q < 4; ++q) acc[mt][nt][q] = 0.f;

    // prefetch one 64-wide K tile: A 1024 chunks, B 1024 chunks (16B each)
    auto prefetch = [&](int kt, int buf) {
        const int k0 = kt * 64;
#pragma unroll
        for (int p = 0; p < 4; ++p) {
            int c  = tid + p * 256;            // 0..1023
            int ra = c >> 3;                   // A row 0..127
            int ka = (c & 7) * 8;              // halves 0..56
            cp_async16(&Asm[buf][ra * GA_STH + ka], &A[(m0 + ra) * 1024 + k0 + ka]);
            int rb = c >> 4;                   // B k-row 0..63
            int nb = (c & 15) * 8;             // halves 0..120
            cp_async16(&Bsm[buf][rb * GB_STH + nb], &W[(k0 + rb) * N + n0 + nb]);
        }
    };

    prefetch(0, 0);
    CP_COMMIT();

    for (int kt = 0; kt < 16; ++kt) {
        if (kt + 1 < 16) prefetch(kt + 1, (kt + 1) & 1);
        CP_COMMIT();
        CP_WAIT1();
        __syncthreads();

        const int buf = kt & 1;
#pragma unroll
        for (int ks = 0; ks < 4; ++ks) {
            uint32_t a[2][4];
#pragma unroll
            for (int mt = 0; mt < 2; ++mt)
                ldsm_x4(a[mt][0], a[mt][1], a[mt][2], a[mt][3],
                        smA[buf] + aOff + (mt * 16 * GA_STH + ks * 16) * 2);
#pragma unroll
            for (int p = 0; p < 4; ++p) {
                uint32_t b0a, b1a, b0b, b1b;
                ldsm_x4_t(b0a, b1a, b0b, b1b,
                          smB[buf] + bOff + (ks * 16 * GB_STH + p * 16) * 2);
#pragma unroll
                for (int mt = 0; mt < 2; ++mt) {
                    mma_f16(acc[mt][2*p][0], acc[mt][2*p][1], acc[mt][2*p][2], acc[mt][2*p][3],
                            a[mt][0], a[mt][1], a[mt][2], a[mt][3], b0a, b1a);
                    mma_f16(acc[mt][2*p+1][0], acc[mt][2*p+1][1], acc[mt][2*p+1][2], acc[mt][2*p+1][3],
                            a[mt][0], a[mt][1], a[mt][2], a[mt][3], b0b, b1b);
                }
            }
        }
        __syncthreads();
    }

    // epilogue
#pragma unroll
    for (int mt = 0; mt < 2; ++mt) {
#pragma unroll
        for (int nt = 0; nt < 8; ++nt) {
            int col = n0 + wn * 64 + nt * 8 + tig * 2;
            float2 bv = *(const float2*)&bias[col];
            int r0 = m0 + wm * 32 + mt * 16 + g;
#pragma unroll
            for (int h = 0; h < 2; ++h) {
                int row = r0 + h * 8;
                float vx = acc[mt][nt][h * 2 + 0] + bv.x;
                float vy = acc[mt][nt][h * 2 + 1] + bv.y;
                if (mode == 0) {
                    float2 v; v.x = vx; v.y = vy;
                    *(float2*)&Out[row * N + col] = v;
                } else {
                    int sec = col >> 10;           // 0:Q 1:K 2:V
                    int rem = col & 1023;
                    int hh  = rem >> 6;
                    int d   = rem & 63;
                    int b   = row >> 11;
                    int t   = row & 2047;
                    __half* dst = (sec == 0) ? Qp : (sec == 1) ? Kp : Vp;
                    *(__half2*)&dst[(((b * HH + hh) * TT + t) << 6) + d] =
                        __floats2half2_rn(vx, vy);
                }
            }
        }
    }
}

// ---------------------------------------------------------------------------
// Flash attention, all fp16 operands (fp32 softmax/accum), balanced pairing:
// each CTA processes q-blocks bx and 15-bx (exactly 34 KV tiles total).
// ---------------------------------------------------------------------------
#define KV_STH 72
#define KV_H (64*KV_STH)                        // 4608 halves / buffer
#define ATTN_SMEM_BYTES (4*KV_H*2)              // 36864

__global__ __launch_bounds__(256, 2)
void attn_f16(const __half* __restrict__ Q, const __half* __restrict__ K,
              const __half* __restrict__ V, __half* __restrict__ O)
{
    extern __shared__ __half smh[];
    __half* Kb[2] = { smh,           smh + KV_H };
    __half* Vb[2] = { smh + 2*KV_H,  smh + 3*KV_H };

    const float NEG_INF = -__int_as_float(0x7f800000);

    const int tid  = threadIdx.x;
    const int wid  = tid >> 5;
    const int lane = tid & 31;
    const int g    = lane >> 2;
    const int tig  = lane & 3;
    const int lr   = lane & 7;
    const int sel  = lane >> 3;
    const int wq   = wid * 16;
    const int head = blockIdx.y;
    const int b    = blockIdx.z;

    const int base = (b * HH + head) * TT * DD;
    const __half* Qg = Q + base;
    const __half* Kg = K + base;
    const __half* Vg = V + base;

    const uint32_t smK[2] = { (uint32_t)__cvta_generic_to_shared(Kb[0]),
                              (uint32_t)__cvta_generic_to_shared(Kb[1]) };
    const uint32_t smV[2] = { (uint32_t)__cvta_generic_to_shared(Vb[0]),
                              (uint32_t)__cvta_generic_to_shared(Vb[1]) };
    const uint32_t kOff = (((sel >> 1) * 8 + lr) * KV_STH + (sel & 1) * 8) * 2;
    const uint32_t vOff = (((sel & 1) * 8 + lr) * KV_STH + (sel >> 1) * 8) * 2;
    const uint32_t qOff = ((wq + (sel & 1) * 8 + lr) * KV_STH + (sel >> 1) * 8) * 2;

    auto prefetch = [&](int jt, int buf) {
        const int k0 = jt * 64;
#pragma unroll
        for (int p = 0; p < 2; ++p) {
            int c  = tid + p * 256;            // 0..511
            int r  = c >> 3;                   // 0..63
            int dc = (c & 7) * 8;              // halves
            cp_async16(&Kb[buf][r * KV_STH + dc], &Kg[(k0 + r) * DD + dc]);
            cp_async16(&Vb[buf][r * KV_STH + dc], &Vg[(k0 + r) * DD + dc]);
        }
    };

#pragma unroll 1
    for (int pass = 0; pass < 2; ++pass) {
        const int qb = pass == 0 ? (int)blockIdx.x : 15 - (int)blockIdx.x;
        const int q0 = qb * 128;

        // ---- stage Q (scaled 0.125) into smem, extract fragments ----
        CP_WAIT0();
        __syncthreads();
        {
            const __half2 sc2 = __float2half2_rn(0.125f);
#pragma unroll
            for (int p = 0; p < 16; ++p) {
                int idx = tid + p * 256;
                int r   = idx >> 5;                // 0..127
                int d2  = (idx & 31);
                __half2 v = *(const __half2*)&Qg[(q0 + r) * DD + d2 * 2];
                *(__half2*)&smh[r * KV_STH + d2 * 2] = __hmul2(v, sc2);
            }
            __syncthreads();
        }
        uint32_t qa[4][4];
        {
            uint32_t qBase = (uint32_t)__cvta_generic_to_shared(smh);
#pragma unroll
            for (int ks = 0; ks < 4; ++ks)
                ldsm_x4(qa[ks][0], qa[ks][1], qa[ks][2], qa[ks][3],
                        qBase + qOff + ks * 32);
            __syncthreads();   // Q reads done before K/V cp.async overwrites
        }

        float o[8][4];
#pragma unroll
        for (int nt = 0; nt < 8; ++nt)
#pragma unroll
            for (int q = 0; q < 4; ++q) o[nt][q] = 0.f;

        float m0 = NEG_INF, m1 = NEG_INF, l0 = 0.f, l1 = 0.f;
        const int row0 = q0 + wq + g;
        const int row1 = row0 + 8;
        const int n_tiles = 2 * (qb + 1);

        prefetch(0, 0);
        CP_COMMIT();

        for (int jt = 0; jt < n_tiles; ++jt) {
            const int k0 = jt * 64;
            if (jt + 1 < n_tiles) prefetch(jt + 1, (jt + 1) & 1);
            CP_COMMIT();
            CP_WAIT1();
            __syncthreads();

            const int buf = jt & 1;

            // ---- S = Q . K^T ----
            float sc[8][4];
#pragma unroll
            for (int nt = 0; nt < 8; ++nt)
#pragma unroll
                for (int q = 0; q < 4; ++q) sc[nt][q] = 0.f;

#pragma unroll
            for (int ks = 0; ks < 4; ++ks) {
#pragma unroll
                for (int p = 0; p < 4; ++p) {
                    uint32_t b0a, b1a, b0b, b1b;
                    ldsm_x4(b0a, b1a, b0b, b1b,
                            smK[buf] + kOff + (p * 16 * KV_STH + ks * 16) * 2);
                    mma_f16(sc[2*p][0], sc[2*p][1], sc[2*p][2], sc[2*p][3],
                            qa[ks][0], qa[ks][1], qa[ks][2], qa[ks][3], b0a, b1a);
                    mma_f16(sc[2*p+1][0], sc[2*p+1][1], sc[2*p+1][2], sc[2*p+1][3],
                            qa[ks][0], qa[ks][1], qa[ks][2], qa[ks][3], b0b, b1b);
                }
            }

            // ---- causal mask ----
            if (k0 + 63 > row0) {
#pragma unroll
                for (int nt = 0; nt < 8; ++nt) {
                    int c0 = k0 + nt * 8 + tig * 2;
                    int c1 = c0 + 1;
                    if (c0 > row0) sc[nt][0] = NEG_INF;
                    if (c1 > row0) sc[nt][1] = NEG_INF;
                    if (c0 > row1) sc[nt][2] = NEG_INF;
                    if (c1 > row1) sc[nt][3] = NEG_INF;
                }
            }

            // ---- in-register online softmax ----
            float mx0 = NEG_INF, mx1 = NEG_INF;
#pragma unroll
            for (int nt = 0; nt < 8; ++nt) {
                mx0 = fmaxf(mx0, fmaxf(sc[nt][0], sc[nt][1]));
                mx1 = fmaxf(mx1, fmaxf(sc[nt][2], sc[nt][3]));
            }
            mx0 = fmaxf(mx0, __shfl_xor_sync(0xffffffffu, mx0, 1));
            mx0 = fmaxf(mx0, __shfl_xor_sync(0xffffffffu, mx0, 2));
            mx1 = fmaxf(mx1, __shfl_xor_sync(0xffffffffu, mx1, 1));
            mx1 = fmaxf(mx1, __shfl_xor_sync(0xffffffffu, mx1, 2));

            float mn0 = fmaxf(m0, mx0);
            float mn1 = fmaxf(m1, mx1);
            float al0 = __expf(m0 - mn0);
            float al1 = __expf(m1 - mn1);
            m0 = mn0; m1 = mn1;

            uint32_t ph[8][2];
            float s0 = 0.f, s1 = 0.f;
#pragma unroll
            for (int nt = 0; nt < 8; ++nt) {
                float p0 = __expf(sc[nt][0] - m0);
                float p1 = __expf(sc[nt][1] - m0);
                float p2 = __expf(sc[nt][2] - m1);
                float p3 = __expf(sc[nt][3] - m1);
                s0 += p0 + p1;
                s1 += p2 + p3;
                __half2 h01 = __floats2half2_rn(p0, p1);
                __half2 h23 = __floats2half2_rn(p2, p3);
                ph[nt][0] = *(uint32_t*)&h01;
                ph[nt][1] = *(uint32_t*)&h23;
            }
            s0 += __shfl_xor_sync(0xffffffffu, s0, 1);
            s0 += __shfl_xor_sync(0xffffffffu, s0, 2);
            s1 += __shfl_xor_sync(0xffffffffu, s1, 1);
            s1 += __shfl_xor_sync(0xffffffffu, s1, 2);
            l0 = l0 * al0 + s0;
            l1 = l1 * al1 + s1;

#pragma unroll
            for (int nt = 0; nt < 8; ++nt) {
                o[nt][0] *= al0; o[nt][1] *= al0;
                o[nt][2] *= al1; o[nt][3] *= al1;
            }

            // ---- O += P @ V ----
#pragma unroll
            for (int c = 0; c < 4; ++c) {
                uint32_t a0 = ph[2*c    ][0];
                uint32_t a1 = ph[2*c    ][1];
                uint32_t a2 = ph[2*c + 1][0];
                uint32_t a3 = ph[2*c + 1][1];
#pragma unroll
                for (int p = 0; p < 4; ++p) {
                    uint32_t b0a, b1a, b0b, b1b;
                    ldsm_x4_t(b0a, b1a, b0b, b1b,
                              smV[buf] + vOff + (c * 16 * KV_STH + p * 16) * 2);
                    mma_f16(o[2*p][0], o[2*p][1], o[2*p][2], o[2*p][3],
                            a0, a1, a2, a3, b0a, b1a);
                    mma_f16(o[2*p+1][0], o[2*p+1][1], o[2*p+1][2], o[2*p+1][3],
                            a0, a1, a2, a3, b0b, b1b);
                }
            }
            __syncthreads();   // buffer reads done before reuse
        }

        // ---- normalize, write fp16 [B,T,C] ----
        float inv0 = 1.f / l0;
        float inv1 = 1.f / l1;
#pragma unroll
        for (int nt = 0; nt < 8; ++nt) {
            int d = head * DD + nt * 8 + tig * 2;
            *(__half2*)&O[(b * TT + row0) * CC + d] =
                __floats2half2_rn(o[nt][0] * inv0, o[nt][1] * inv0);
            *(__half2*)&O[(b * TT + row1) * CC + d] =
                __floats2half2_rn(o[nt][2] * inv1, o[nt][3] * inv1);
        }
    }
}

// ---------------------------------------------------------------------------
extern "C" void kernel_launch(void* const* d_in, const int* in_sizes, int n_in,
                              void* d_out, int out_size)
{
    const float* x    = (const float*)d_in[0];  // [4,2048,1024]
    const float* Wqkv = (const float*)d_in[1];  // [1024,3072]
    const float* bqkv = (const float*)d_in[2];  // [3072]
    const float* Wo   = (const float*)d_in[3];  // [1024,1024]
    const float* bo   = (const float*)d_in[4];  // [1024]
    float* out = (float*)d_out;                 // [4,2048,1024]

    __half *xh, *wqkvh, *woh, *gQ, *gK, *gV, *gAtt;
    cudaGetSymbolAddress((void**)&xh,    g_xh);
    cudaGetSymbolAddress((void**)&wqkvh, g_wqkvh);
    cudaGetSymbolAddress((void**)&woh,   g_woh);
    cudaGetSymbolAddress((void**)&gQ,    g_Q);
    cudaGetSymbolAddress((void**)&gK,    g_K);
    cudaGetSymbolAddress((void**)&gV,    g_V);
    cudaGetSymbolAddress((void**)&gAtt,  g_Att);

    cudaFuncSetAttribute(gemm_f16, cudaFuncAttributeMaxDynamicSharedMemorySize,
                         GEMM_SMEM_BYTES);
    cudaFuncSetAttribute(attn_f16, cudaFuncAttributeMaxDynamicSharedMemorySize,
                         ATTN_SMEM_BYTES);

    // 0) convert inputs to fp16
    cvt_half_kernel<<<(M_TOT*CC/4 + 255)/256, 256>>>(x, xh, M_TOT*CC);
    cvt_half_kernel<<<(CC*3*CC/4 + 255)/256, 256>>>(Wqkv, wqkvh, CC*3*CC);
    cvt_half_kernel<<<(CC*CC/4 + 255)/256, 256>>>(Wo, woh, CC*CC);

    // 1) QKV projection + fp16 scatter to [B,H,T,D]
    gemm_f16<<<dim3(3072 / 128, M_TOT / 128), 256, GEMM_SMEM_BYTES>>>(
        xh, wqkvh, bqkv, nullptr, gQ, gK, gV, 3072, 1);

    // 2) causal flash attention -> fp16 [B,T,C] (paired q-blocks, balanced)
    attn_f16<<<dim3(8, HH, BB), 256, ATTN_SMEM_BYTES>>>(gQ, gK, gV, gAtt);

    // 3) output projection (fp16 in, fp32 out)
    gemm_f16<<<dim3(1024 / 128, M_TOT / 128), 256, GEMM_SMEM_BYTES>>>(
        gAtt, woh, bo, out, nullptr, nullptr, nullptr, 1024, 0);
}